// round 1
// baseline (speedup 1.0000x reference)
#include <cuda_runtime.h>
#include <cstdint>

// ---------------- problem constants ----------------
#define B      32
#define C0     16
#define H0     128
#define W0     128
#define C1     64      // channels after unshuffle
#define H1     64
#define W1     64
#define NTOK   4096    // H1*W1
#define NS     256     // SAMPLES^2
#define KNN    3

// ---------------- scratch (no allocations allowed) ----------------
__device__ float g_xtok[B * NTOK * C1];        // [b][n][c]  33.5 MB
__device__ float g_xs  [B * NS * C1];          // [b][m][c]   2 MB
__device__ float g_m2  [B * NS];               // sample norms
__device__ float g_wt  [C1 * 3 * C1];          // [(c*3+k)*64 + o]
__device__ float g_y   [B * NS * 3 * C1];      // [b][m][k][o] (bias folded into k=0)
__device__ int4  g_idx [B * NTOK];             // top-3 sample indices per token

// round(linspace(0, 63, 16)) — verified against f32 linspace rounding
__device__ const int SAMP[16] = {0,4,8,13,17,21,25,29,34,38,42,46,50,55,59,63};

// ---------------- kernel 1: pixel_unshuffle into token-major layout ----------------
__global__ void unshuffle_kernel(const float* __restrict__ x) {
    unsigned gid = blockIdx.x * 256u + threadIdx.x;      // < B*NTOK*C1 = 8388608
    unsigned c1 = gid & 63u;
    unsigned n  = (gid >> 6) & 4095u;
    unsigned b  = gid >> 18;
    unsigned h1 = n >> 6, w1 = n & 63u;
    unsigned c = c1 >> 2, sh = (c1 >> 1) & 1u, sw = c1 & 1u;
    g_xtok[gid] = x[((b * C0 + c) * H0 + (2u * h1 + sh)) * W0 + (2u * w1 + sw)];
}

// ---------------- kernel 2: extract sampled tokens + their squared norms ----------------
__global__ void sample_kernel(const float* __restrict__ x) {
    int pair = blockIdx.x;              // b*256 + m
    int b = pair >> 8, m = pair & 255;
    int h1 = SAMP[m >> 4], w1 = SAMP[m & 15];
    int c1 = threadIdx.x;               // 64 threads
    int c = c1 >> 2, sh = (c1 >> 1) & 1, sw = c1 & 1;
    float v = x[((b * C0 + c) * H0 + (2 * h1 + sh)) * W0 + (2 * w1 + sw)];
    g_xs[pair * C1 + c1] = v;
    __shared__ float red[64];
    red[c1] = v * v;
    __syncthreads();
    if (c1 < 32) {
        float s = red[c1] + red[c1 + 32];
        #pragma unroll
        for (int off = 16; off; off >>= 1)
            s += __shfl_down_sync(0xffffffffu, s, off);
        if (c1 == 0) g_m2[pair] = s;
    }
}

// ---------------- kernel 3: transpose weight to [(c,k), o] for coalesced reads ----------------
__global__ void wt_kernel(const float* __restrict__ w) {
    int d = blockIdx.x * 256 + threadIdx.x;   // < 64*192 = 12288
    int o = d & 63;
    int ck = d >> 6;                          // c*3 + k
    int c = ck / 3, k = ck - 3 * c;
    g_wt[d] = w[o * 192 + c * 3 + k];
}

// ---------------- kernel 4: Y[b][m][k][o] = W_k @ xs[b][m]  (bias into k=0) ----------------
__global__ __launch_bounds__(256) void y_kernel(const float* __restrict__ bias) {
    int mi = threadIdx.x >> 6;                // 0..3
    int o  = threadIdx.x & 63;
    int pair = blockIdx.x * 4 + mi;           // < B*NS = 8192
    __shared__ float s_xs[4][64];
    s_xs[mi][o] = g_xs[pair * C1 + o];
    __syncthreads();
    float a0 = bias[o], a1 = 0.f, a2 = 0.f;
    #pragma unroll 8
    for (int c = 0; c < 64; c++) {
        float xv = s_xs[mi][c];
        a0 = fmaf(xv, g_wt[(c * 3 + 0) * 64 + o], a0);
        a1 = fmaf(xv, g_wt[(c * 3 + 1) * 64 + o], a1);
        a2 = fmaf(xv, g_wt[(c * 3 + 2) * 64 + o], a2);
    }
    float* yp = g_y + (size_t)pair * 192;
    yp[o] = a0; yp[64 + o] = a1; yp[128 + o] = a2;
}

// ---------------- kernel 5: distance GEMM + fused top-3 (the hot kernel) ----------------
// Per block: 256 tokens, samples streamed through SMEM in two 128-sample tiles.
// Inner product uses packed fma.rn.f32x2 (2 fp32 FMA / instr) — doubles fp32 rate on sm_103a.
__global__ __launch_bounds__(256, 2) void score_topk_kernel() {
    __shared__ float4 s_xs4[128 * 16];       // 128 samples x 64 floats = 32 KB
    __shared__ float  s_m2[128];
    const int b   = blockIdx.y;
    const int tok = blockIdx.x * 256 + threadIdx.x;

    // token vector -> 32 packed f32x2 registers
    unsigned long long tq[32];
    const float4* tv = (const float4*)(g_xtok + ((size_t)b * NTOK + tok) * C1);
    #pragma unroll
    for (int j = 0; j < 16; j++) {
        float4 f = tv[j];
        asm("mov.b64 %0, {%1,%2};" : "=l"(tq[2 * j])     : "f"(f.x), "f"(f.y));
        asm("mov.b64 %0, {%1,%2};" : "=l"(tq[2 * j + 1]) : "f"(f.z), "f"(f.w));
    }

    float b0 = 3.4e38f, b1 = 3.4e38f, b2 = 3.4e38f;
    int   i0 = 0, i1 = 0, i2 = 0;
    unsigned sbase = (unsigned)__cvta_generic_to_shared(s_xs4);

    for (int half = 0; half < 2; half++) {
        __syncthreads();
        const float4* src = (const float4*)(g_xs + ((size_t)b * NS + half * 128) * C1);
        #pragma unroll
        for (int j = 0; j < 8; j++)
            s_xs4[threadIdx.x + 256 * j] = src[threadIdx.x + 256 * j];
        if (threadIdx.x < 128)
            s_m2[threadIdx.x] = g_m2[b * NS + half * 128 + threadIdx.x];
        __syncthreads();

        #pragma unroll 1
        for (int m = 0; m < 128; m++) {
            unsigned addr = sbase + m * 256;
            unsigned long long a0 = 0, a1 = 0, a2 = 0, a3 = 0;
            #pragma unroll
            for (int j = 0; j < 16; j += 2) {
                unsigned long long q0, q1, q2, q3;
                asm volatile("ld.shared.v2.u64 {%0,%1}, [%2];"
                             : "=l"(q0), "=l"(q1) : "r"(addr + j * 16));
                asm volatile("ld.shared.v2.u64 {%0,%1}, [%2];"
                             : "=l"(q2), "=l"(q3) : "r"(addr + j * 16 + 16));
                asm("fma.rn.f32x2 %0, %1, %2, %0;" : "+l"(a0) : "l"(tq[2 * j]),     "l"(q0));
                asm("fma.rn.f32x2 %0, %1, %2, %0;" : "+l"(a1) : "l"(tq[2 * j + 1]), "l"(q1));
                asm("fma.rn.f32x2 %0, %1, %2, %0;" : "+l"(a2) : "l"(tq[2 * j + 2]), "l"(q2));
                asm("fma.rn.f32x2 %0, %1, %2, %0;" : "+l"(a3) : "l"(tq[2 * j + 3]), "l"(q3));
            }
            asm("add.rn.f32x2 %0, %0, %1;" : "+l"(a0) : "l"(a2));
            asm("add.rn.f32x2 %0, %0, %1;" : "+l"(a1) : "l"(a3));
            asm("add.rn.f32x2 %0, %0, %1;" : "+l"(a0) : "l"(a1));
            float lo, hi;
            asm("mov.b64 {%0,%1}, %2;" : "=f"(lo), "=f"(hi) : "l"(a0));
            float v = fmaf(-2.f, lo + hi, s_m2[m]);   // m2 - 2*dot: same order as d2
            int gm = half * 128 + m;
            // strict < keeps earlier index on ties -> matches stable top_k
            if (v < b2) {
                if (v < b1) {
                    b2 = b1; i2 = i1;
                    if (v < b0) { b1 = b0; i1 = i0; b0 = v; i0 = gm; }
                    else        { b1 = v;  i1 = gm; }
                } else { b2 = v; i2 = gm; }
            }
        }
    }
    g_idx[(size_t)b * NTOK + tok] = make_int4(i0, i1, i2, 0);
}

// ---------------- kernel 6: gather Y by idx, add, pixel_shuffle write ----------------
__global__ __launch_bounds__(256) void gather_out_kernel(float* __restrict__ out) {
    const int b = blockIdx.y;
    const int n = blockIdx.x * 256 + threadIdx.x;
    int4 id = g_idx[(size_t)b * NTOK + n];

    float4 acc[16];
    const float4* y0 = (const float4*)(g_y + ((size_t)(b * NS) + id.x) * 192);
    #pragma unroll
    for (int j = 0; j < 16; j++) acc[j] = y0[j];
    const float4* y1 = (const float4*)(g_y + ((size_t)(b * NS) + id.y) * 192 + 64);
    #pragma unroll
    for (int j = 0; j < 16; j++) {
        float4 v = y1[j];
        acc[j].x += v.x; acc[j].y += v.y; acc[j].z += v.z; acc[j].w += v.w;
    }
    const float4* y2 = (const float4*)(g_y + ((size_t)(b * NS) + id.z) * 192 + 128);
    #pragma unroll
    for (int j = 0; j < 16; j++) {
        float4 v = y2[j];
        acc[j].x += v.x; acc[j].y += v.y; acc[j].z += v.z; acc[j].w += v.w;
    }

    int h1 = n >> 6, w1 = n & 63;
    float* ob = out + (size_t)b * C0 * (H0 * W0);
    // o = co*4 + sh*2 + sw  ->  out[b][co][2h1+sh][2w1+sw]
    #pragma unroll
    for (int co = 0; co < 16; co++) {
        *(float2*)(ob + co * (H0 * W0) + (2 * h1)     * W0 + 2 * w1) = make_float2(acc[co].x, acc[co].y);
        *(float2*)(ob + co * (H0 * W0) + (2 * h1 + 1) * W0 + 2 * w1) = make_float2(acc[co].z, acc[co].w);
    }
}

// ---------------- launcher ----------------
extern "C" void kernel_launch(void* const* d_in, const int* in_sizes, int n_in,
                              void* d_out, int out_size) {
    const float* x    = (const float*)d_in[0];
    const float* w    = (const float*)d_in[1];
    const float* bias = (const float*)d_in[2];
    float* out = (float*)d_out;

    unshuffle_kernel<<<(B * NTOK * C1) / 256, 256>>>(x);
    sample_kernel<<<B * NS, 64>>>(x);
    wt_kernel<<<(C1 * 3 * C1) / 256, 256>>>(w);
    y_kernel<<<(B * NS) / 4, 256>>>(bias);
    score_topk_kernel<<<dim3(NTOK / 256, B), 256>>>();
    gather_out_kernel<<<dim3(NTOK / 256, B), 256>>>(out);
}

// round 4
// speedup vs baseline: 1.0932x; 1.0932x over previous
#include <cuda_runtime.h>
#include <cstdint>

// ---------------- problem constants ----------------
#define B      32
#define C0     16
#define H0     128
#define W0     128
#define C1     64
#define NTOK   4096
#define NS     256

// ---------------- scratch (16B-aligned: everything below gets wide-cast) ----------------
__device__ __align__(16) float  g_xtok[B * NTOK * C1];      // [b][n][c]
__device__ __align__(16) float  g_xs  [B * NS * C1];        // [b][m][c]
__device__ __align__(16) float2 g_m2h [B * NS];             // {-0.5*|xs|^2, 0}
__device__ __align__(16) float  g_wt2 [C1 * 3 * C1];        // [(k*64+o)*64 + c]
__device__ __align__(16) float  g_y   [B * NS * 3 * C1];    // [pair][k*64+o]
__device__ __align__(16) int4   g_idx [B * NTOK];

__device__ const int SAMP[16] = {0,4,8,13,17,21,25,29,34,38,42,46,50,55,59,63};

#define FMA2(a,x,y) asm("fma.rn.f32x2 %0, %1, %2, %0;" : "+l"(a) : "l"(x), "l"(y))
#define ADD2(a,b)   asm("add.rn.f32x2 %0, %0, %1;" : "+l"(a) : "l"(b))
#define UNPK(lo,hi,a) asm("mov.b64 {%0,%1}, %2;" : "=f"(lo), "=f"(hi) : "l"(a))

// ---------------- kernel 1: pixel_unshuffle (coalesced both sides via smem) ----------
// one block = one (b, h1) row of 64 tokens
__global__ __launch_bounds__(256) void unshuffle_kernel(const float* __restrict__ x) {
    __shared__ __align__(16) float s[128 * 33];   // s[w][cc], w=0..127, cc=2c+sh
    int b  = blockIdx.x >> 6;
    int h1 = blockIdx.x & 63;
    int t  = threadIdx.x;
    const float* xb = x + (size_t)b * C0 * H0 * W0;
    #pragma unroll
    for (int i = 0; i < 4; i++) {
        int idx = t + 256 * i;            // 0..1023
        int r   = idx >> 5;               // 0..31 = 2c+sh
        int w4  = idx & 31;
        int c = r >> 1, sh = r & 1;
        float4 v = *(const float4*)(xb + ((size_t)c * H0 + (2 * h1 + sh)) * W0 + w4 * 4);
        s[(4 * w4 + 0) * 33 + r] = v.x;
        s[(4 * w4 + 1) * 33 + r] = v.y;
        s[(4 * w4 + 2) * 33 + r] = v.z;
        s[(4 * w4 + 3) * 33 + r] = v.w;
    }
    __syncthreads();
    float* dst = g_xtok + ((size_t)b * NTOK + h1 * 64) * C1;
    #pragma unroll
    for (int i = 0; i < 4; i++) {
        int idx = t + 256 * i;            // token w1 = idx>>4, channel-quad q = idx&15
        int w1 = idx >> 4, q = idx & 15;
        // value(c=q, sh, sw) = s[2*w1+sw][2*q+sh]   — SCALAR loads (odd rows are 4B-offset)
        int r0 = (2 * w1) * 33, r1 = (2 * w1 + 1) * 33;
        *(float4*)(dst + idx * 4) = make_float4(
            s[r0 + 2 * q],     s[r1 + 2 * q],
            s[r0 + 2 * q + 1], s[r1 + 2 * q + 1]);
    }
}

// ---------------- kernel 2: sampled tokens + packed init {-0.5*m2, 0} ----------------
__global__ void sample_kernel(const float* __restrict__ x) {
    int pair = blockIdx.x;
    int b = pair >> 8, m = pair & 255;
    int h1 = SAMP[m >> 4], w1 = SAMP[m & 15];
    int c1 = threadIdx.x;
    int c = c1 >> 2, sh = (c1 >> 1) & 1, sw = c1 & 1;
    float v = x[((size_t)(b * C0 + c) * H0 + (2 * h1 + sh)) * W0 + (2 * w1 + sw)];
    g_xs[(size_t)pair * C1 + c1] = v;
    __shared__ float red[64];
    red[c1] = v * v;
    __syncthreads();
    if (c1 < 32) {
        float s = red[c1] + red[c1 + 32];
        #pragma unroll
        for (int off = 16; off; off >>= 1)
            s += __shfl_down_sync(0xffffffffu, s, off);
        if (c1 == 0) g_m2h[pair] = make_float2(-0.5f * s, 0.f);
    }
}

// ---------------- kernel 3: weight -> [k][o][c] (per-thread-contiguous) ----------------
__global__ void wt_kernel(const float* __restrict__ w) {
    int d = blockIdx.x * 256 + threadIdx.x;   // < 12288 = ((k*64+o)*64+c)
    int c = d & 63;
    int ko = d >> 6;
    int o = ko & 63, k = ko >> 6;
    g_wt2[d] = w[o * 192 + c * 3 + k];
}

// ---------------- kernel 4: Y[pair][k*64+o] = sum_c xs[pair][c]*W[c][k][o] (+bias k=0) --
// 192 threads = (k,o); weights live in registers (packed f32x2); xs broadcast via smem.
__global__ __launch_bounds__(192) void y_kernel(const float* __restrict__ bias) {
    int t = threadIdx.x;
    int o = t & 63;
    unsigned long long wq[32];
    const ulonglong2* wp = (const ulonglong2*)(g_wt2 + (size_t)t * 64);   // 256B stride: 16B aligned
    #pragma unroll
    for (int j = 0; j < 16; j++) { ulonglong2 v = wp[j]; wq[2 * j] = v.x; wq[2 * j + 1] = v.y; }

    __shared__ __align__(16) float s_xs[64 * 64];   // 64 pairs x 64 channels
    const float4* src = (const float4*)(g_xs + (size_t)blockIdx.x * 64 * 64);
    for (int i = t; i < 1024; i += 192) ((float4*)s_xs)[i] = src[i];
    __syncthreads();

    float bo = (t < 64) ? bias[o] : 0.f;
    float* yb = g_y + (size_t)blockIdx.x * 64 * 192;
    #pragma unroll 1
    for (int p0 = 0; p0 < 64; p0 += 8) {
        unsigned long long acc[8] = {0,0,0,0,0,0,0,0};
        #pragma unroll
        for (int j = 0; j < 32; j++) {
            #pragma unroll
            for (int p = 0; p < 8; p++) {
                unsigned long long xq = *(const unsigned long long*)&s_xs[(p0 + p) * 64 + 2 * j]; // even idx
                FMA2(acc[p], wq[j], xq);
            }
        }
        #pragma unroll
        for (int p = 0; p < 8; p++) {
            float lo, hi; UNPK(lo, hi, acc[p]);
            yb[(size_t)(p0 + p) * 192 + t] = lo + hi + bo;
        }
    }
}

// ---------------- kernel 5: distance scores + fused top-3 (hot kernel) ----------------
// score s = dot(token, sample) - 0.5*|sample|^2  (rank-equivalent to -d2; larger = nearer)
__global__ __launch_bounds__(256, 2) void score_topk_kernel() {
    __shared__ ulonglong2 s_xs[128 * 16];             // 128 samples x 64 floats
    __shared__ unsigned long long s_in[128];          // packed {-0.5*m2, 0}
    const int b   = blockIdx.y;
    const int tok = blockIdx.x * 256 + threadIdx.x;

    unsigned long long tq[32];
    const ulonglong2* tv = (const ulonglong2*)(g_xtok + ((size_t)b * NTOK + tok) * C1);
    #pragma unroll
    for (int j = 0; j < 16; j++) { ulonglong2 v = tv[j]; tq[2 * j] = v.x; tq[2 * j + 1] = v.y; }

    float t0 = -3.4e38f, t1 = -3.4e38f, t2 = -3.4e38f;
    int   i0 = 0, i1 = 0, i2 = 0;

    for (int half = 0; half < 2; half++) {
        __syncthreads();
        const ulonglong2* src = (const ulonglong2*)(g_xs + ((size_t)b * NS + half * 128) * C1);
        #pragma unroll
        for (int j = 0; j < 8; j++)
            s_xs[threadIdx.x + 256 * j] = src[threadIdx.x + 256 * j];
        if (threadIdx.x < 128)
            s_in[threadIdx.x] = ((const unsigned long long*)g_m2h)[b * NS + half * 128 + threadIdx.x];
        __syncthreads();

        #pragma unroll 2
        for (int m = 0; m < 128; m++) {
            unsigned long long a0 = s_in[m];           // {-0.5*m2, 0}
            unsigned long long a1 = 0, a2 = 0, a3 = 0;
            #pragma unroll
            for (int j = 0; j < 8; j++) {
                ulonglong2 qa = s_xs[m * 16 + 2 * j];
                ulonglong2 qb = s_xs[m * 16 + 2 * j + 1];
                FMA2(a0, tq[4 * j + 0], qa.x);
                FMA2(a1, tq[4 * j + 1], qa.y);
                FMA2(a2, tq[4 * j + 2], qb.x);
                FMA2(a3, tq[4 * j + 3], qb.y);
            }
            ADD2(a0, a2); ADD2(a1, a3); ADD2(a0, a1);
            float lo, hi; UNPK(lo, hi, a0);
            float s = lo + hi;
            int gm = half * 128 + m;
            // strict > keeps earlier index on ties (matches stable top_k)
            if (s > t2) {
                if (s > t1) {
                    t2 = t1; i2 = i1;
                    if (s > t0) { t1 = t0; i1 = i0; t0 = s; i0 = gm; }
                    else        { t1 = s;  i1 = gm; }
                } else { t2 = s; i2 = gm; }
            }
        }
    }
    g_idx[(size_t)b * NTOK + tok] = make_int4(i0, i1, i2, 0);
}

// ---------------- kernel 6: gather Y by idx, add, pixel_shuffle write ----------------
__global__ __launch_bounds__(256) void gather_out_kernel(float* __restrict__ out) {
    const int b = blockIdx.y;
    const int n = blockIdx.x * 256 + threadIdx.x;
    int4 id = g_idx[(size_t)b * NTOK + n];

    float4 acc[16];
    const float4* y0 = (const float4*)(g_y + ((size_t)(b * NS) + id.x) * 192);
    #pragma unroll
    for (int j = 0; j < 16; j++) acc[j] = y0[j];
    const float4* y1 = (const float4*)(g_y + ((size_t)(b * NS) + id.y) * 192 + 64);
    #pragma unroll
    for (int j = 0; j < 16; j++) {
        float4 v = y1[j];
        acc[j].x += v.x; acc[j].y += v.y; acc[j].z += v.z; acc[j].w += v.w;
    }
    const float4* y2 = (const float4*)(g_y + ((size_t)(b * NS) + id.z) * 192 + 128);
    #pragma unroll
    for (int j = 0; j < 16; j++) {
        float4 v = y2[j];
        acc[j].x += v.x; acc[j].y += v.y; acc[j].z += v.z; acc[j].w += v.w;
    }

    int h1 = n >> 6, w1 = n & 63;
    float* ob = out + (size_t)b * C0 * (H0 * W0);
    #pragma unroll
    for (int co = 0; co < 16; co++) {
        *(float2*)(ob + co * (H0 * W0) + (2 * h1)     * W0 + 2 * w1) = make_float2(acc[co].x, acc[co].y);
        *(float2*)(ob + co * (H0 * W0) + (2 * h1 + 1) * W0 + 2 * w1) = make_float2(acc[co].z, acc[co].w);
    }
}

// ---------------- launcher ----------------
extern "C" void kernel_launch(void* const* d_in, const int* in_sizes, int n_in,
                              void* d_out, int out_size) {
    const float* x    = (const float*)d_in[0];
    const float* w    = (const float*)d_in[1];
    const float* bias = (const float*)d_in[2];
    float* out = (float*)d_out;

    unshuffle_kernel<<<B * 64, 256>>>(x);
    sample_kernel<<<B * NS, 64>>>(x);
    wt_kernel<<<48, 256>>>(w);
    y_kernel<<<B * NS / 64, 192>>>(bias);
    score_topk_kernel<<<dim3(NTOK / 256, B), 256>>>();
    gather_out_kernel<<<dim3(NTOK / 256, B), 256>>>(out);
}